// round 11
// baseline (speedup 1.0000x reference)
#include <cuda_runtime.h>
#include <cstdint>

// TemporalSpike RLeaky recurrence — R10: global byte-LUT through L1.
//   rec = spk_prev @ W^T + b_lin  (binary spk -> warp-uniform ballot mask ->
//                                  4 byte lookups in a 128KB __device__ LUT)
//   mem = 0.9*mem + x_t + rec - spk ;  spk = (mem > 1)
// x (16,128,512,32); W (32,32); b (32). Out: spikes then mems, concatenated.
//
// Structure = R9 (8 warps/block, 4-step tiles, 4-stage cp.async x staging,
// streaming stores). Change: the recurrent LUT moves from smem (8 LDS/step)
// to a global 4x256x32 byte-table read via __ldg (4 coalesced L1-hit LDG),
// halving L1/shared wavefronts and freeing 16KB smem per block.

#define BB 16
#define TT 128
#define NN 512
#define FF 32
#define ROWS (BB * NN)
#define WPB 8
#define TSTRIDE (NN * FF)          // 16384 floats between t-slices
#define TILE 4
#define NTILE (TT / TILE)          // 32
#define NSTAGE 4
#define XS_TILE (TILE * WPB * FF)  // 1024 floats = 4KB per stage

// tabg[p][v][g]: p = byte position (0..3), v = byte value, g = lane.
// Entry = sum of W[g][8p+j] over set bits j of v; bias folded into p==0.
__device__ float tabg[4 * 256 * 32];   // 128 KB

__global__ void build_lut_kernel(const float* __restrict__ W,
                                 const float* __restrict__ b_lin)
{
    const int e = blockIdx.x * 256 + threadIdx.x;   // 0..32767
    const int g = e & 31;
    const int v = (e >> 5) & 255;
    const int p = e >> 13;
    float s = (p == 0) ? b_lin[g] : 0.0f;
    const float* wr = W + g * FF + 8 * p;
    #pragma unroll
    for (int j = 0; j < 8; j++)
        if (v & (1 << j)) s += wr[j];
    tabg[e] = s;
}

__device__ __forceinline__ void cp_async16(uint32_t saddr, const void* gaddr) {
    asm volatile("cp.async.cg.shared.global [%0], [%1], 16;\n"
                 :: "r"(saddr), "l"(gaddr) : "memory");
}
#define CP_COMMIT() asm volatile("cp.async.commit_group;\n" ::: "memory")
#define CP_WAIT(n)  asm volatile("cp.async.wait_group %0;\n" :: "n"(n) : "memory")

__global__ __launch_bounds__(WPB * 32, 6)
void temporal_spike_kernel(const float* __restrict__ x,
                           float* __restrict__ out)
{
    __shared__ float xs[NSTAGE][XS_TILE];     // 16 KB staging, 4 stages

    const int tid  = threadIdx.x;
    const int lane = tid & 31;
    const int w    = tid >> 5;

    const int blk = blockIdx.x;
    const int b   = blk >> 6;                 // 64 blocks per batch
    const int n0  = (blk & 63) * WPB;         // 8 consecutive rows
    const size_t base_blk = ((size_t)b * TT * NN + n0) * FF;

    // Staging role: thread -> (t-slice in tile, 16B chunk within the 1KB slice)
    const int ti = tid >> 6;                  // 0..3
    const int q  = tid & 63;                  // 0..63
    const float* gsrc = x + base_blk + (size_t)ti * TSTRIDE + q * 4;
    const uint32_t sbase = (uint32_t)__cvta_generic_to_shared(&xs[0][0])
                         + (ti * (WPB * FF) + q * 4) * 4;

    // Prologue: issue tiles 0..2 into stages 0..2 (3 groups in flight).
    #pragma unroll
    for (int k = 0; k < NSTAGE - 1; k++) {
        cp_async16(sbase + k * (XS_TILE * 4), gsrc + (size_t)k * TILE * TSTRIDE);
        CP_COMMIT();
    }

    float* sp = out + base_blk + w * FF + lane;            // spikes
    float* mp = sp + (size_t)BB * TT * NN * FF;            // mems

    // Per-lane LUT base pointers (byte index is warp-uniform -> coalesced line).
    const float* t0 = tabg + lane;
    const float* t1 = t0 + 1 * 256 * 32;
    const float* t2 = t0 + 2 * 256 * 32;
    const float* t3 = t0 + 3 * 256 * 32;

    float mem = 0.0f, spk = 0.0f;
    unsigned mask = 0u;
    const float* xv = &xs[0][0] + w * FF + lane;

    for (int k = 0; k < NTILE; k++) {
        // Keep 3 tiles ahead in flight; then wait for tile k.
        if (k + NSTAGE - 1 < NTILE) {
            cp_async16(sbase + ((k + NSTAGE - 1) & (NSTAGE - 1)) * (XS_TILE * 4),
                       gsrc + (size_t)(k + NSTAGE - 1) * TILE * TSTRIDE);
            CP_COMMIT();
            CP_WAIT(3);
        } else if (k == NTILE - 3) {
            CP_WAIT(2);
        } else if (k == NTILE - 2) {
            CP_WAIT(1);
        } else {
            CP_WAIT(0);
        }
        __syncthreads();   // tile k visible to all warps

        const float* xt = xv + (k & (NSTAGE - 1)) * XS_TILE;
        #pragma unroll
        for (int s = 0; s < TILE; s++) {
            const float xval = xt[s * (WPB * FF)];

            const unsigned b0 =  mask        & 255u;
            const unsigned b1 = (mask >>  8) & 255u;
            const unsigned b2 = (mask >> 16) & 255u;
            const unsigned b3 =  mask >> 24;
            const float r0 = __ldg(t0 + b0 * 32);
            const float r1 = __ldg(t1 + b1 * 32);
            const float r2 = __ldg(t2 + b2 * 32);
            const float r3 = __ldg(t3 + b3 * 32);
            const float rec = (r0 + r1) + (r2 + r3);

            mem = fmaf(0.9f, mem, xval + rec - spk);    // THRESH=1
            const bool fire = (mem > 1.0f);
            spk = fire ? 1.0f : 0.0f;
            mask = __ballot_sync(0xffffffffu, fire);

            const size_t off = (size_t)(k * TILE + s) * TSTRIDE;
            __stcs(sp + off, spk);
            __stcs(mp + off, mem);
        }
        __syncthreads();   // release buffer (k & 3) before refill
    }
}

extern "C" void kernel_launch(void* const* d_in, const int* in_sizes, int n_in,
                              void* d_out, int out_size)
{
    const float* x     = (const float*)d_in[0];
    const float* W     = (const float*)d_in[1];
    const float* b_lin = (const float*)d_in[2];
    float* out = (float*)d_out;

    // Moderate carveout: ~96KB shared (6 blocks x 16KB) so >=128KB of L1
    // remains to hold the byte-LUT resident.
    cudaFuncSetAttribute(temporal_spike_kernel,
                         cudaFuncAttributePreferredSharedMemoryCarveout, 42);

    build_lut_kernel<<<128, 256>>>(W, b_lin);

    dim3 grid(ROWS / WPB);     // 1024
    dim3 block(WPB * 32);      // 256
    temporal_spike_kernel<<<grid, block>>>(x, out);
}

// round 13
// speedup vs baseline: 1.2412x; 1.2412x over previous
#include <cuda_runtime.h>
#include <cstdint>

// TemporalSpike RLeaky recurrence — R11: byte-LUT + single-wave occupancy.
//   rec = spk_prev @ W^T + b_lin  (binary spk -> warp-uniform ballot mask ->
//                                  4 byte lookups in a 128KB __device__ LUT)
//   mem = 0.9*mem + x_t + rec - spk ;  spk = (mem > 1)
// x (16,128,512,32); W (32,32); b (32). Out: spikes then mems, concatenated.
//
// vs R10: staging shrunk to 3 stages x 4KB (12KB/block) so SEVEN blocks fit
// per SM under the ~100KB effective shared budget -> 1036 >= 1024 blocks in
// ONE wave (R10 ran 5/SM -> 284-block tail wave at half occupancy).

#define BB 16
#define TT 128
#define NN 512
#define FF 32
#define ROWS (BB * NN)
#define WPB 8
#define TSTRIDE (NN * FF)          // 16384 floats between t-slices
#define TILE 4
#define NTILE (TT / TILE)          // 32
#define NSTAGE 3
#define XS_TILE (TILE * WPB * FF)  // 1024 floats = 4KB per stage

// tabg[p][v][g]: p = byte position (0..3), v = byte value, g = lane.
// Entry = sum of W[g][8p+j] over set bits j of v; bias folded into p==0.
__device__ float tabg[4 * 256 * 32];   // 128 KB

__global__ void build_lut_kernel(const float* __restrict__ W,
                                 const float* __restrict__ b_lin)
{
    const int e = blockIdx.x * 512 + threadIdx.x;   // 0..32767
    const int g = e & 31;
    const int v = (e >> 5) & 255;
    const int p = e >> 13;
    float s = (p == 0) ? b_lin[g] : 0.0f;
    const float* wr = W + g * FF + 8 * p;
    #pragma unroll
    for (int j = 0; j < 8; j++)
        if (v & (1 << j)) s += wr[j];
    tabg[e] = s;
}

__device__ __forceinline__ void cp_async16(uint32_t saddr, const void* gaddr) {
    asm volatile("cp.async.cg.shared.global [%0], [%1], 16;\n"
                 :: "r"(saddr), "l"(gaddr) : "memory");
}
#define CP_COMMIT() asm volatile("cp.async.commit_group;\n" ::: "memory")
#define CP_WAIT(n)  asm volatile("cp.async.wait_group %0;\n" :: "n"(n) : "memory")

__global__ __launch_bounds__(WPB * 32, 7)
void temporal_spike_kernel(const float* __restrict__ x,
                           float* __restrict__ out)
{
    __shared__ float xs[NSTAGE][XS_TILE];     // 12 KB staging, 3 stages

    const int tid  = threadIdx.x;
    const int lane = tid & 31;
    const int w    = tid >> 5;

    const int blk = blockIdx.x;
    const int b   = blk >> 6;                 // 64 blocks per batch
    const int n0  = (blk & 63) * WPB;         // 8 consecutive rows
    const size_t base_blk = ((size_t)b * TT * NN + n0) * FF;

    // Staging role: thread -> (t-slice in tile, 16B chunk within the 1KB slice)
    const int ti = tid >> 6;                  // 0..3
    const int q  = tid & 63;                  // 0..63
    const float* gsrc = x + base_blk + (size_t)ti * TSTRIDE + q * 4;
    const uint32_t sbase = (uint32_t)__cvta_generic_to_shared(&xs[0][0])
                         + (ti * (WPB * FF) + q * 4) * 4;

    // Prologue: tiles 0..1 into stages 0..1 (2 groups in flight).
    #pragma unroll
    for (int k = 0; k < NSTAGE - 1; k++) {
        cp_async16(sbase + k * (XS_TILE * 4), gsrc + (size_t)k * TILE * TSTRIDE);
        CP_COMMIT();
    }

    float* sp = out + base_blk + w * FF + lane;            // spikes
    float* mp = sp + (size_t)BB * TT * NN * FF;            // mems

    // Per-lane LUT base pointers (byte index warp-uniform -> one coalesced line).
    const float* t0 = tabg + lane;
    const float* t1 = t0 + 1 * 256 * 32;
    const float* t2 = t0 + 2 * 256 * 32;
    const float* t3 = t0 + 3 * 256 * 32;

    float mem = 0.0f, spk = 0.0f;
    unsigned mask = 0u;
    const float* xv = &xs[0][0] + w * FF + lane;

    int buf = 0;       // = k % NSTAGE
    int fbuf = NSTAGE - 1;  // buffer for tile k+NSTAGE-1
    for (int k = 0; k < NTILE; k++) {
        // Keep 2 tiles ahead in flight; then wait for tile k.
        if (k + NSTAGE - 1 < NTILE) {
            cp_async16(sbase + fbuf * (XS_TILE * 4),
                       gsrc + (size_t)(k + NSTAGE - 1) * TILE * TSTRIDE);
            CP_COMMIT();
            CP_WAIT(2);                        // 3 pending -> tile k complete
        } else if (k == NTILE - 2) {
            CP_WAIT(1);
        } else {                               // k == NTILE-1
            CP_WAIT(0);
        }
        __syncthreads();   // tile k visible to all warps

        const float* xt = xv + buf * XS_TILE;
        #pragma unroll
        for (int s = 0; s < TILE; s++) {
            const float xval = xt[s * (WPB * FF)];

            const unsigned b0 =  mask        & 255u;
            const unsigned b1 = (mask >>  8) & 255u;
            const unsigned b2 = (mask >> 16) & 255u;
            const unsigned b3 =  mask >> 24;
            const float r0 = __ldg(t0 + b0 * 32);
            const float r1 = __ldg(t1 + b1 * 32);
            const float r2 = __ldg(t2 + b2 * 32);
            const float r3 = __ldg(t3 + b3 * 32);
            const float rec = (r0 + r1) + (r2 + r3);

            mem = fmaf(0.9f, mem, xval + rec - spk);    // THRESH=1
            const bool fire = (mem > 1.0f);
            spk = fire ? 1.0f : 0.0f;
            mask = __ballot_sync(0xffffffffu, fire);

            const size_t off = (size_t)(k * TILE + s) * TSTRIDE;
            __stcs(sp + off, spk);
            __stcs(mp + off, mem);
        }
        __syncthreads();   // release buffer `buf` before it is refilled

        buf  = (buf  == NSTAGE - 1) ? 0 : buf + 1;
        fbuf = (fbuf == NSTAGE - 1) ? 0 : fbuf + 1;
    }
}

extern "C" void kernel_launch(void* const* d_in, const int* in_sizes, int n_in,
                              void* d_out, int out_size)
{
    const float* x     = (const float*)d_in[0];
    const float* W     = (const float*)d_in[1];
    const float* b_lin = (const float*)d_in[2];
    float* out = (float*)d_out;

    build_lut_kernel<<<64, 512>>>(W, b_lin);

    dim3 grid(ROWS / WPB);     // 1024
    dim3 block(WPB * 32);      // 256
    temporal_spike_kernel<<<grid, block>>>(x, out);
}